// round 12
// baseline (speedup 1.0000x reference)
#include <cuda_runtime.h>
#include <cstdint>

// LGA: out[n,c,h,w] = sum_{i,j in 5x5} in1[n,c,h+i-2,w+j-2] * in2[n,i*5+j,h,w]
// Shapes fixed: in1 [4,32,384,768] f32, in2 [4,25,384,768] f32.
//
// Round-12 = round-7 pipeline + shuffle-halo reads.
//  - Each thread's 4 own pixels are ONE aligned LDS.128 per tap row
//    (conflict-free, wavefront-optimal). The 2-float left/right halos come
//    from neighbor lanes via __shfl_up/down (shuffle unit, not the smem
//    crossbar); boundary lanes (tx==0 / tx==15) override with a tiny
//    predicated LDS.64 from the staged halo columns.
//  - Crossbar read traffic drops 40 -> ~21 B/output; staging stays 16B cp16.
//  - Everything else identical to round 7 (best: 92.9us): 4-stage cp.async
//    ring of channel pairs, 100 taps in registers, packed fma.rn.f32x2.

#define NDIM 4
#define CDIM 32
#define HDIM 384
#define WDIM 768
#define KTAPS 25
#define PLANE (HDIM * WDIM)

#define BX 16
#define BY 8
#define NTHR (BX * BY)                // 128
#define TILE_W 64                     // 16 threads * 4 px
#define TILE_H 8
#define SROWS (TILE_H + 4)            // 12
#define SPITCH 72                     // floats per smem row (288 B, 16B-mult)
#define STAGE_ELEMS (SROWS * SPITCH)  // 864
#define STAGES 4                      // ring of channel PAIRS
#define NPAIR (CDIM / 2)              // 16
#define CHUNKS_PER_ROW 18             // 18 x 16B = 72 floats
#define NCHUNK (SROWS * CHUNKS_PER_ROW)  // 216

typedef unsigned long long u64;

__device__ __forceinline__ uint32_t smem_u32(const void* p) {
    return (uint32_t)__cvta_generic_to_shared(p);
}
__device__ __forceinline__ void cp_async16(uint32_t dst, const float* src, int sz) {
    asm volatile("cp.async.cg.shared.global [%0], [%1], 16, %2;\n"
                 :: "r"(dst), "l"(src), "r"(sz));
}
__device__ __forceinline__ void cp_commit() {
    asm volatile("cp.async.commit_group;\n" ::: "memory");
}
__device__ __forceinline__ void cp_wait2() {
    asm volatile("cp.async.wait_group 2;\n" ::: "memory");
}
__device__ __forceinline__ u64 pack2(float lo, float hi) {
    u64 r;
    asm("mov.b64 %0, {%1, %2};" : "=l"(r) : "f"(lo), "f"(hi));
    return r;
}
__device__ __forceinline__ void unpack2(u64 v, float& lo, float& hi) {
    asm("mov.b64 {%0, %1}, %2;" : "=f"(lo), "=f"(hi) : "l"(v));
}
__device__ __forceinline__ void fma2(u64& acc, u64 a, u64 b) {
    asm("fma.rn.f32x2 %0, %1, %2, %0;" : "+l"(acc) : "l"(a), "l"(b));
}

__global__ __launch_bounds__(NTHR, 3)
void lga_kernel(const float* __restrict__ in1,
                const float* __restrict__ in2,
                float* __restrict__ out) {
    __shared__ __align__(16) float ring[STAGES][2][STAGE_ELEMS];

    const int tx = threadIdx.x;            // 0..15
    const int ty = threadIdx.y;            // 0..7
    const int tid = ty * BX + tx;
    const int wbase = blockIdx.x * TILE_W;
    const int hbase = blockIdx.y * TILE_H;
    const int n = blockIdx.z;

    const int h = hbase + ty;              // output row
    const int w0 = wbase + 4 * tx;         // first of 4 output cols

    const bool isL = (tx == 0);
    const bool isR = (tx == BX - 1);

    // ---- 25 per-pixel weight quads -> 50 packed f32x2 registers ----
    u64 w01[KTAPS], w23[KTAPS];
    {
        const float* wp = in2 + ((size_t)n * KTAPS * HDIM + h) * WDIM + w0;
#pragma unroll
        for (int t = 0; t < KTAPS; t++) {
            float4 v = __ldcs((const float4*)(wp + (size_t)t * PLANE));
            w01[t] = pack2(v.x, v.y);
            w23[t] = pack2(v.z, v.w);
        }
    }

    // ---- copy roles: up to 2 16B chunks per thread per channel ----
    const float* in1n = in1 + (size_t)n * CDIM * PLANE;
    int  goff0 = 0, goff1 = 0, cpsz0 = 0, cpsz1 = 0, soff0 = 0, soff1 = 0;
    bool act1 = false;
    {
        int k = tid;                                  // chunk 0 (always active)
        int r = k / CHUNKS_PER_ROW, ch = k - r * CHUNKS_PER_ROW;
        int gy = hbase - 2 + r, gx0 = wbase - 4 + 4 * ch;
        bool v = (gy >= 0) && (gy < HDIM) && (gx0 >= 0) && (gx0 + 3 < WDIM);
        goff0 = v ? (gy * WDIM + gx0) : 0;
        cpsz0 = v ? 16 : 0;
        soff0 = r * SPITCH + 4 * ch;

        k = tid + NTHR;                               // chunk 1
        act1 = (k < NCHUNK);
        r = k / CHUNKS_PER_ROW; ch = k - r * CHUNKS_PER_ROW;
        gy = hbase - 2 + r; gx0 = wbase - 4 + 4 * ch;
        v = act1 && (gy >= 0) && (gy < HDIM) && (gx0 >= 0) && (gx0 + 3 < WDIM);
        goff1 = v ? (gy * WDIM + gx0) : 0;
        cpsz1 = v ? 16 : 0;
        soff1 = r * SPITCH + 4 * ch;
    }

    float* po = out + (size_t)n * CDIM * PLANE + (size_t)h * WDIM + w0;

    auto issue = [&](int p, int s) {
        const float* srcA = in1n + (size_t)(2 * p) * PLANE;
        const float* srcB = srcA + PLANE;
        uint32_t dA = smem_u32(&ring[s][0][0]);
        uint32_t dB = smem_u32(&ring[s][1][0]);
        cp_async16(dA + 4 * soff0, srcA + goff0, cpsz0);
        cp_async16(dB + 4 * soff0, srcB + goff0, cpsz0);
        if (act1) {
            cp_async16(dA + 4 * soff1, srcA + goff1, cpsz1);
            cp_async16(dB + 4 * soff1, srcB + goff1, cpsz1);
        }
        cp_commit();
    };

    // ---- prologue: pairs 0..2 (channels 0..5) in flight ----
    issue(0, 0);
    issue(1, 1);
    issue(2, 2);

#pragma unroll 1
    for (int p = 0; p < NPAIR; p++) {
        const int s = p & (STAGES - 1);

        cp_wait2();
        __syncthreads();

        if (p + 3 < NPAIR) issue(p + 3, (p + 3) & (STAGES - 1));
        else               cp_commit();

#pragma unroll
        for (int half = 0; half < 2; half++) {
            // row r of this thread's window lives at tile row (ty+i);
            // own 4 px (cols w0..w0+3) = tile float offset 4tx+4 (16B aligned)
            const float* rowp = &ring[s][half][ty * SPITCH];
            u64 acc01 = 0, acc23 = 0;
#pragma unroll
            for (int i = 0; i < 5; i++) {
                const float* rp = rowp + i * SPITCH;
                float4 M = *(const float4*)(rp + 4 * tx + 4);   // LDS.128

                // halo via shuffle from neighbor lanes' M
                float Lz = __shfl_up_sync(0xffffffffu, M.z, 1);
                float Lw = __shfl_up_sync(0xffffffffu, M.w, 1);
                float Rx = __shfl_down_sync(0xffffffffu, M.x, 1);
                float Ry = __shfl_down_sync(0xffffffffu, M.y, 1);
                if (isL) {                       // cols wbase-2, wbase-1
                    float2 t = *(const float2*)(rp + 2);
                    Lz = t.x; Lw = t.y;
                }
                if (isR) {                       // cols wbase+64, wbase+65
                    float2 t = *(const float2*)(rp + 68);
                    Rx = t.x; Ry = t.y;
                }

                u64 p01 = pack2(Lz, Lw);
                u64 p12 = pack2(Lw, M.x);
                u64 p23 = pack2(M.x, M.y);
                u64 p34 = pack2(M.y, M.z);
                u64 p45 = pack2(M.z, M.w);
                u64 p56 = pack2(M.w, Rx);
                u64 p67 = pack2(Rx, Ry);

                const u64* wr01 = &w01[5 * i];
                const u64* wr23 = &w23[5 * i];
                fma2(acc01, p01, wr01[0]);
                fma2(acc23, p23, wr23[0]);
                fma2(acc01, p12, wr01[1]);
                fma2(acc23, p34, wr23[1]);
                fma2(acc01, p23, wr01[2]);
                fma2(acc23, p45, wr23[2]);
                fma2(acc01, p34, wr01[3]);
                fma2(acc23, p56, wr23[3]);
                fma2(acc01, p45, wr01[4]);
                fma2(acc23, p67, wr23[4]);
            }
            float4 o;
            unpack2(acc01, o.x, o.y);
            unpack2(acc23, o.z, o.w);
            __stcs((float4*)(po + (size_t)(2 * p + half) * PLANE), o);
        }
    }
}

extern "C" void kernel_launch(void* const* d_in, const int* in_sizes, int n_in,
                              void* d_out, int out_size) {
    const float* in1 = (const float*)d_in[0];
    const float* in2 = (const float*)d_in[1];
    float* out = (float*)d_out;

    dim3 block(BX, BY);
    dim3 grid(WDIM / TILE_W, HDIM / TILE_H, NDIM);  // 12 x 48 x 4
    lga_kernel<<<grid, block>>>(in1, in2, out);
}

// round 14
// speedup vs baseline: 1.5698x; 1.5698x over previous
#include <cuda_runtime.h>
#include <cstdint>

// LGA: out[n,c,h,w] = sum_{i,j in 5x5} in1[n,c,h+i-2,w+j-2] * in2[n,i*5+j,h,w]
// Shapes fixed: in1 [4,32,384,768] f32, in2 [4,25,384,768] f32.
//
// Round-14 = round-13 (staggered output grid, conflict-free LDS.128 windows)
// with the global-side 128-bit accesses split into 8B-aligned 64-bit ones
// (round-13 trapped: w0 == 2 mod 4 makes float4 global ld/st misaligned).
//  - Thread output quad starts at w0 = 64*bx + 4*tx - 2, so its 8-float input
//    window (w0-2 .. w0+5) is 16B-aligned in the staged tile: per tap row the
//    whole window is TWO aligned LDS.128 — conflict-free, 8 wavefronts/row vs
//    round-7's 12. No halo loads, no shuffles.
//  - Weights: 2x float2 LDG per tap (one-time). Output: 2x float2 STG/channel.
//  - Pipeline identical to round 7 (best: 92.9us): 4-stage cp.async ring of
//    channel pairs, 100 taps in registers, packed fma.rn.f32x2.

#define NDIM 4
#define CDIM 32
#define HDIM 384
#define WDIM 768
#define KTAPS 25
#define PLANE (HDIM * WDIM)

#define BX 16
#define BY 8
#define NTHR (BX * BY)                // 128
#define TILE_H 8
#define SROWS (TILE_H + 4)            // 12
#define SPITCH 72                     // floats per smem row (288 B, 16B-mult)
#define STAGE_ELEMS (SROWS * SPITCH)  // 864
#define STAGES 4                      // ring of channel PAIRS
#define NPAIR (CDIM / 2)              // 16
#define CHUNKS_PER_ROW 18             // 18 x 16B = 72 floats
#define NCHUNK (SROWS * CHUNKS_PER_ROW)  // 216
#define GRIDX 13                      // staggered quads cover [-2, 770)

typedef unsigned long long u64;

__device__ __forceinline__ uint32_t smem_u32(const void* p) {
    return (uint32_t)__cvta_generic_to_shared(p);
}
__device__ __forceinline__ void cp_async16(uint32_t dst, const float* src, int sz) {
    asm volatile("cp.async.cg.shared.global [%0], [%1], 16, %2;\n"
                 :: "r"(dst), "l"(src), "r"(sz));
}
__device__ __forceinline__ void cp_commit() {
    asm volatile("cp.async.commit_group;\n" ::: "memory");
}
__device__ __forceinline__ void cp_wait2() {
    asm volatile("cp.async.wait_group 2;\n" ::: "memory");
}
__device__ __forceinline__ u64 pack2(float lo, float hi) {
    u64 r;
    asm("mov.b64 %0, {%1, %2};" : "=l"(r) : "f"(lo), "f"(hi));
    return r;
}
__device__ __forceinline__ void unpack2(u64 v, float& lo, float& hi) {
    asm("mov.b64 {%0, %1}, %2;" : "=f"(lo), "=f"(hi) : "l"(v));
}
__device__ __forceinline__ void fma2(u64& acc, u64 a, u64 b) {
    asm("fma.rn.f32x2 %0, %1, %2, %0;" : "+l"(acc) : "l"(a), "l"(b));
}

__global__ __launch_bounds__(NTHR, 3)
void lga_kernel(const float* __restrict__ in1,
                const float* __restrict__ in2,
                float* __restrict__ out) {
    __shared__ __align__(16) float ring[STAGES][2][STAGE_ELEMS];

    const int tx = threadIdx.x;            // 0..15
    const int ty = threadIdx.y;            // 0..7
    const int tid = ty * BX + tx;
    const int hbase = blockIdx.y * TILE_H;
    const int n = blockIdx.z;

    const int h  = hbase + ty;                       // output row
    const int w0 = 64 * blockIdx.x + 4 * tx - 2;     // first of 4 output cols
    const int G0 = 64 * blockIdx.x - 8;              // staged tile col0 (16B al)

    const bool fullq = (w0 >= 0) && (w0 <= WDIM - 4);    // whole quad in image
    const bool loEdge = (w0 == -2);                      // cols 0,1 valid (.z,.w)
    const bool hiEdge = (w0 == WDIM - 2);                // cols 766,767 (.x,.y)

    // ---- 25 per-pixel weight quads -> 50 packed f32x2 registers ----
    // global side is only 8B-aligned (w0 == 2 mod 4) -> use float2 loads
    u64 w01[KTAPS], w23[KTAPS];
    {
        const float* wrow = in2 + ((size_t)n * KTAPS * HDIM + h) * WDIM;
#pragma unroll
        for (int t = 0; t < KTAPS; t++) {
            const float* wp = wrow + (size_t)t * PLANE;
            if (fullq) {
                float2 a = __ldcs((const float2*)(wp + w0));
                float2 b = __ldcs((const float2*)(wp + w0 + 2));
                w01[t] = pack2(a.x, a.y);
                w23[t] = pack2(b.x, b.y);
            } else if (loEdge) {
                float2 b = __ldcs((const float2*)(wp + 0));
                w01[t] = 0;
                w23[t] = pack2(b.x, b.y);
            } else if (hiEdge) {
                float2 a = __ldcs((const float2*)(wp + (WDIM - 2)));
                w01[t] = pack2(a.x, a.y);
                w23[t] = 0;
            } else {
                w01[t] = 0;
                w23[t] = 0;
            }
        }
    }

    // ---- copy roles: up to 2 16B chunks per thread per channel ----
    const float* in1n = in1 + (size_t)n * CDIM * PLANE;
    int  goff0 = 0, goff1 = 0, cpsz0 = 0, cpsz1 = 0, soff0 = 0, soff1 = 0;
    bool act1 = false;
    {
        int k = tid;                                  // chunk 0 (always active)
        int r = k / CHUNKS_PER_ROW, ch = k - r * CHUNKS_PER_ROW;
        int gy = hbase - 2 + r, gx0 = G0 + 4 * ch;
        bool v = (gy >= 0) && (gy < HDIM) && (gx0 >= 0) && (gx0 + 3 < WDIM);
        goff0 = v ? (gy * WDIM + gx0) : 0;
        cpsz0 = v ? 16 : 0;
        soff0 = r * SPITCH + 4 * ch;

        k = tid + NTHR;                               // chunk 1
        act1 = (k < NCHUNK);
        r = k / CHUNKS_PER_ROW; ch = k - r * CHUNKS_PER_ROW;
        gy = hbase - 2 + r; gx0 = G0 + 4 * ch;
        v = act1 && (gy >= 0) && (gy < HDIM) && (gx0 >= 0) && (gx0 + 3 < WDIM);
        goff1 = v ? (gy * WDIM + gx0) : 0;
        cpsz1 = v ? 16 : 0;
        soff1 = r * SPITCH + 4 * ch;
    }

    float* pon = out + (size_t)n * CDIM * PLANE + (size_t)h * WDIM;

    auto issue = [&](int p, int s) {
        const float* srcA = in1n + (size_t)(2 * p) * PLANE;
        const float* srcB = srcA + PLANE;
        uint32_t dA = smem_u32(&ring[s][0][0]);
        uint32_t dB = smem_u32(&ring[s][1][0]);
        cp_async16(dA + 4 * soff0, srcA + goff0, cpsz0);
        cp_async16(dB + 4 * soff0, srcB + goff0, cpsz0);
        if (act1) {
            cp_async16(dA + 4 * soff1, srcA + goff1, cpsz1);
            cp_async16(dB + 4 * soff1, srcB + goff1, cpsz1);
        }
        cp_commit();
    };

    // ---- prologue: pairs 0..2 (channels 0..5) in flight ----
    issue(0, 0);
    issue(1, 1);
    issue(2, 2);

#pragma unroll 1
    for (int p = 0; p < NPAIR; p++) {
        const int s = p & (STAGES - 1);

        cp_wait2();
        __syncthreads();

        if (p + 3 < NPAIR) issue(p + 3, (p + 3) & (STAGES - 1));
        else               cp_commit();

#pragma unroll
        for (int half = 0; half < 2; half++) {
            // window (w0-2 .. w0+5) = staged offsets 4tx+4 .. 4tx+11:
            // exactly two aligned LDS.128 per tap row, conflict-free.
            const float* basep = &ring[s][half][ty * SPITCH + 4 * tx + 4];
            u64 acc01 = 0, acc23 = 0;
#pragma unroll
            for (int i = 0; i < 5; i++) {
                const float* rp = basep + i * SPITCH;
                float4 Q1 = *(const float4*)(rp);       // d0..d3
                float4 Q2 = *(const float4*)(rp + 4);   // d4..d7

                u64 p01 = pack2(Q1.x, Q1.y);
                u64 p12 = pack2(Q1.y, Q1.z);
                u64 p23 = pack2(Q1.z, Q1.w);
                u64 p34 = pack2(Q1.w, Q2.x);
                u64 p45 = pack2(Q2.x, Q2.y);
                u64 p56 = pack2(Q2.y, Q2.z);
                u64 p67 = pack2(Q2.z, Q2.w);

                const u64* wr01 = &w01[5 * i];
                const u64* wr23 = &w23[5 * i];
                fma2(acc01, p01, wr01[0]);
                fma2(acc23, p23, wr23[0]);
                fma2(acc01, p12, wr01[1]);
                fma2(acc23, p34, wr23[1]);
                fma2(acc01, p23, wr01[2]);
                fma2(acc23, p45, wr23[2]);
                fma2(acc01, p34, wr01[3]);
                fma2(acc23, p56, wr23[3]);
                fma2(acc01, p45, wr01[4]);
                fma2(acc23, p67, wr23[4]);
            }
            float o0, o1, o2, o3;
            unpack2(acc01, o0, o1);
            unpack2(acc23, o2, o3);
            float* pc = pon + (size_t)(2 * p + half) * PLANE;
            if (fullq) {
                __stcs((float2*)(pc + w0),     make_float2(o0, o1));
                __stcs((float2*)(pc + w0 + 2), make_float2(o2, o3));
            } else if (loEdge) {
                __stcs((float2*)(pc + 0), make_float2(o2, o3));
            } else if (hiEdge) {
                __stcs((float2*)(pc + (WDIM - 2)), make_float2(o0, o1));
            }
        }
    }
}

extern "C" void kernel_launch(void* const* d_in, const int* in_sizes, int n_in,
                              void* d_out, int out_size) {
    const float* in1 = (const float*)d_in[0];
    const float* in2 = (const float*)d_in[1];
    float* out = (float*)d_out;

    dim3 block(BX, BY);
    dim3 grid(GRIDX, HDIM / TILE_H, NDIM);  // 13 x 48 x 4
    lga_kernel<<<grid, block>>>(in1, in2, out);
}

// round 15
// speedup vs baseline: 1.5837x; 1.0088x over previous
#include <cuda_runtime.h>
#include <cstdint>

// LGA: out[n,c,h,w] = sum_{i,j in 5x5} in1[n,c,h+i-2,w+j-2] * in2[n,i*5+j,h,w]
// Shapes fixed: in1 [4,32,384,768] f32, in2 [4,25,384,768] f32.
//
// Round-15 = round-14 (staggered grid, conflict-free two-LDS.128 windows) +
//  1) row-lookahead: next tap row's LDS issued before current row's FMAs
//  2) 4 accumulator chains per channel (even/odd rows) -> no FMA RAW stalls
//  3) quad-channel ring: 3 stages x 4 channels, one wait+barrier per 4
//     channels (8 cadences total vs 16).

#define NDIM 4
#define CDIM 32
#define HDIM 384
#define WDIM 768
#define KTAPS 25
#define PLANE (HDIM * WDIM)

#define BX 16
#define BY 8
#define NTHR (BX * BY)                // 128
#define TILE_H 8
#define SROWS (TILE_H + 4)            // 12
#define SPITCH 72                     // floats per smem row (288 B)
#define STAGE_ELEMS (SROWS * SPITCH)  // 864
#define STAGES 3                      // ring of channel QUADS
#define NQUAD (CDIM / 4)              // 8
#define CHUNKS_PER_ROW 18             // 18 x 16B = 72 floats
#define NCHUNK (SROWS * CHUNKS_PER_ROW)  // 216
#define GRIDX 13                      // staggered quads cover [-2, 770)

typedef unsigned long long u64;

__device__ __forceinline__ uint32_t smem_u32(const void* p) {
    return (uint32_t)__cvta_generic_to_shared(p);
}
__device__ __forceinline__ void cp_async16(uint32_t dst, const float* src, int sz) {
    asm volatile("cp.async.cg.shared.global [%0], [%1], 16, %2;\n"
                 :: "r"(dst), "l"(src), "r"(sz));
}
__device__ __forceinline__ void cp_commit() {
    asm volatile("cp.async.commit_group;\n" ::: "memory");
}
__device__ __forceinline__ void cp_wait1() {
    asm volatile("cp.async.wait_group 1;\n" ::: "memory");
}
__device__ __forceinline__ u64 pack2(float lo, float hi) {
    u64 r;
    asm("mov.b64 %0, {%1, %2};" : "=l"(r) : "f"(lo), "f"(hi));
    return r;
}
__device__ __forceinline__ void unpack2(u64 v, float& lo, float& hi) {
    asm("mov.b64 {%0, %1}, %2;" : "=f"(lo), "=f"(hi) : "l"(v));
}
__device__ __forceinline__ void fma2(u64& acc, u64 a, u64 b) {
    asm("fma.rn.f32x2 %0, %1, %2, %0;" : "+l"(acc) : "l"(a), "l"(b));
}

__global__ __launch_bounds__(NTHR, 3)
void lga_kernel(const float* __restrict__ in1,
                const float* __restrict__ in2,
                float* __restrict__ out) {
    __shared__ __align__(16) float ring[STAGES][4][STAGE_ELEMS];  // 41.5 KB

    const int tx = threadIdx.x;            // 0..15
    const int ty = threadIdx.y;            // 0..7
    const int tid = ty * BX + tx;
    const int hbase = blockIdx.y * TILE_H;
    const int n = blockIdx.z;

    const int h  = hbase + ty;                       // output row
    const int w0 = 64 * blockIdx.x + 4 * tx - 2;     // first of 4 output cols
    const int G0 = 64 * blockIdx.x - 8;              // staged tile col0 (16B al)

    const bool fullq = (w0 >= 0) && (w0 <= WDIM - 4);
    const bool loEdge = (w0 == -2);                  // cols 0,1 valid (.z,.w)
    const bool hiEdge = (w0 == WDIM - 2);            // cols 766,767 (.x,.y)

    // ---- 25 per-pixel weight quads -> 50 packed f32x2 registers ----
    u64 w01[KTAPS], w23[KTAPS];
    {
        const float* wrow = in2 + ((size_t)n * KTAPS * HDIM + h) * WDIM;
#pragma unroll
        for (int t = 0; t < KTAPS; t++) {
            const float* wp = wrow + (size_t)t * PLANE;
            if (fullq) {
                float2 a = __ldcs((const float2*)(wp + w0));
                float2 b = __ldcs((const float2*)(wp + w0 + 2));
                w01[t] = pack2(a.x, a.y);
                w23[t] = pack2(b.x, b.y);
            } else if (loEdge) {
                float2 b = __ldcs((const float2*)(wp + 0));
                w01[t] = 0;
                w23[t] = pack2(b.x, b.y);
            } else if (hiEdge) {
                float2 a = __ldcs((const float2*)(wp + (WDIM - 2)));
                w01[t] = pack2(a.x, a.y);
                w23[t] = 0;
            } else {
                w01[t] = 0;
                w23[t] = 0;
            }
        }
    }

    // ---- copy roles: up to 2 16B chunks per thread per channel ----
    const float* in1n = in1 + (size_t)n * CDIM * PLANE;
    int  goff0 = 0, goff1 = 0, cpsz0 = 0, cpsz1 = 0, soff0 = 0, soff1 = 0;
    bool act1 = false;
    {
        int k = tid;
        int r = k / CHUNKS_PER_ROW, ch = k - r * CHUNKS_PER_ROW;
        int gy = hbase - 2 + r, gx0 = G0 + 4 * ch;
        bool v = (gy >= 0) && (gy < HDIM) && (gx0 >= 0) && (gx0 + 3 < WDIM);
        goff0 = v ? (gy * WDIM + gx0) : 0;
        cpsz0 = v ? 16 : 0;
        soff0 = r * SPITCH + 4 * ch;

        k = tid + NTHR;
        act1 = (k < NCHUNK);
        r = k / CHUNKS_PER_ROW; ch = k - r * CHUNKS_PER_ROW;
        gy = hbase - 2 + r; gx0 = G0 + 4 * ch;
        v = act1 && (gy >= 0) && (gy < HDIM) && (gx0 >= 0) && (gx0 + 3 < WDIM);
        goff1 = v ? (gy * WDIM + gx0) : 0;
        cpsz1 = v ? 16 : 0;
        soff1 = r * SPITCH + 4 * ch;
    }

    float* pon = out + (size_t)n * CDIM * PLANE + (size_t)h * WDIM;

    // issue the copy of channel quad q into stage s (one commit group)
    auto issue = [&](int q, int s) {
#pragma unroll
        for (int ch = 0; ch < 4; ch++) {
            const float* src = in1n + (size_t)(4 * q + ch) * PLANE;
            uint32_t d = smem_u32(&ring[s][ch][0]);
            cp_async16(d + 4 * soff0, src + goff0, cpsz0);
            if (act1) cp_async16(d + 4 * soff1, src + goff1, cpsz1);
        }
        cp_commit();
    };

    // ---- prologue: quads 0,1 (channels 0..7) in flight ----
    issue(0, 0);
    issue(1, 1);

#pragma unroll 1
    for (int q = 0; q < NQUAD; q++) {
        const int s = q % STAGES;

        cp_wait1();          // quad q complete (quad q+1 still flying)
        __syncthreads();     // visibility + ring-reuse fence

        if (q + 2 < NQUAD) issue(q + 2, (q + 2) % STAGES);
        else               cp_commit();   // keep wait-count math fixed

        // ---- compute the 4 channels of this quad ----
#pragma unroll
        for (int ch = 0; ch < 4; ch++) {
            const float* basep = &ring[s][ch][ty * SPITCH + 4 * tx + 4];
            // 4 accumulator chains: even rows -> A, odd rows -> B
            u64 a01A = 0, a01B = 0, a23A = 0, a23B = 0;

            float4 Q1 = *(const float4*)(basep);        // row 0: d0..d3
            float4 Q2 = *(const float4*)(basep + 4);    // row 0: d4..d7
#pragma unroll
            for (int i = 0; i < 5; i++) {
                float4 N1, N2;
                if (i < 4) {                             // lookahead row i+1
                    const float* np = basep + (i + 1) * SPITCH;
                    N1 = *(const float4*)(np);
                    N2 = *(const float4*)(np + 4);
                }
                u64 p01 = pack2(Q1.x, Q1.y);
                u64 p12 = pack2(Q1.y, Q1.z);
                u64 p23 = pack2(Q1.z, Q1.w);
                u64 p34 = pack2(Q1.w, Q2.x);
                u64 p45 = pack2(Q2.x, Q2.y);
                u64 p56 = pack2(Q2.y, Q2.z);
                u64 p67 = pack2(Q2.z, Q2.w);

                const u64* wr01 = &w01[5 * i];
                const u64* wr23 = &w23[5 * i];
                u64& acc01 = (i & 1) ? a01B : a01A;
                u64& acc23 = (i & 1) ? a23B : a23A;
                fma2(acc01, p01, wr01[0]);
                fma2(acc23, p23, wr23[0]);
                fma2(acc01, p12, wr01[1]);
                fma2(acc23, p34, wr23[1]);
                fma2(acc01, p23, wr01[2]);
                fma2(acc23, p45, wr23[2]);
                fma2(acc01, p34, wr01[3]);
                fma2(acc23, p56, wr23[3]);
                fma2(acc01, p45, wr01[4]);
                fma2(acc23, p67, wr23[4]);

                Q1 = N1;
                Q2 = N2;
            }
            float xA, yA, xB, yB, zA, wA, zB, wB;
            unpack2(a01A, xA, yA);
            unpack2(a01B, xB, yB);
            unpack2(a23A, zA, wA);
            unpack2(a23B, zB, wB);
            float o0 = xA + xB, o1 = yA + yB, o2 = zA + zB, o3 = wA + wB;

            float* pc = pon + (size_t)(4 * q + ch) * PLANE;
            if (fullq) {
                __stcs((float2*)(pc + w0),     make_float2(o0, o1));
                __stcs((float2*)(pc + w0 + 2), make_float2(o2, o3));
            } else if (loEdge) {
                __stcs((float2*)(pc + 0), make_float2(o2, o3));
            } else if (hiEdge) {
                __stcs((float2*)(pc + (WDIM - 2)), make_float2(o0, o1));
            }
        }
    }
}

extern "C" void kernel_launch(void* const* d_in, const int* in_sizes, int n_in,
                              void* d_out, int out_size) {
    const float* in1 = (const float*)d_in[0];
    const float* in2 = (const float*)d_in[1];
    float* out = (float*)d_out;

    dim3 block(BX, BY);
    dim3 grid(GRIDX, HDIM / TILE_H, NDIM);  // 13 x 48 x 4
    lga_kernel<<<grid, block>>>(in1, in2, out);
}